// round 2
// baseline (speedup 1.0000x reference)
#include <cuda_runtime.h>
#include <math.h>

// Problem dims
#define Bq   8
#define Tq   1024
#define Dq   4096
#define Hq   4
#define HSq  1024
#define BT   8192          // B*T
#define FFq  20480         // 5*D

// ---------------- scratch (__device__ globals; no allocations) ----------------
__device__ float g_q   [(size_t)Hq*BT*HSq];     // [H][B*T][HS]
__device__ float g_k   [(size_t)Hq*BT*HSq];
__device__ float g_v   [(size_t)Hq*BT*HSq];
__device__ float g_w   [(size_t)Hq*Bq*Tq*Tq];   // [H][B][T][T]
__device__ float g_ocat[(size_t)BT*Dq];         // [B][T][H*HS]
__device__ float g_srcA[(size_t)BT*Dq];
__device__ float g_wp  [(size_t)Hq*BT*Dq];      // [H][B*T][D]
__device__ float g_o2  [(size_t)BT*Dq];         // [B][T][H*T]
__device__ float g_o3  [(size_t)BT*Dq];
__device__ float g_trgf[(size_t)BT*Dq];
__device__ float g_ln2 [(size_t)BT*Dq];
__device__ float g_h1  [(size_t)BT*FFq];
__device__ float g_ff  [(size_t)BT*Dq];

__device__ __forceinline__ float gelu_exact(float x) {
    return 0.5f * x * (1.0f + erff(x * 0.70710678118654752440f));
}

// ---------------- generic batched SGEMM: C = alpha*A@op(B) (+bias) (+gelu) ---
// A: [M,K] row-major (lda=K). B: NN -> [K,N] (ldb=N); NT -> [N,K] (ldb=K).
// C row stride = ldc. Batch z = z1*batch2 + z2 with independent strides.
// 128x128x8 tile, 256 threads, 8x8 per thread.
template<bool TB>
__global__ __launch_bounds__(256, 2)
void sgemm(const float* __restrict__ A, const float* __restrict__ B,
           const float* __restrict__ bias, float* __restrict__ C,
           int M, int N, int K, int ldc, int batch2,
           long sA1, long sA2, long sB1, long sB2, long sC1, long sC2, long sBias1,
           float alpha, int act)
{
    int z  = blockIdx.z;
    int z1 = z / batch2, z2 = z % batch2;
    A += z1 * sA1 + z2 * sA2;
    B += z1 * sB1 + z2 * sB2;
    C += z1 * sC1 + z2 * sC2;
    if (bias) bias += z1 * sBias1;

    __shared__ float As[8][132];
    __shared__ float Bs[8][132];

    int tid  = threadIdx.x;
    int brow = blockIdx.y * 128;
    int bcol = blockIdx.x * 128;
    int lr = tid >> 1;            // 0..127
    int lc = (tid & 1) * 4;       // 0 or 4
    int ty = tid >> 4, tx = tid & 15;

    float acc[8][8];
#pragma unroll
    for (int i = 0; i < 8; i++)
#pragma unroll
        for (int j = 0; j < 8; j++) acc[i][j] = 0.f;

    for (int k0 = 0; k0 < K; k0 += 8) {
        float4 av = *(const float4*)(A + (long)(brow + lr) * K + k0 + lc);
        As[lc + 0][lr] = av.x; As[lc + 1][lr] = av.y;
        As[lc + 2][lr] = av.z; As[lc + 3][lr] = av.w;
        if (TB) {
            float4 bv = *(const float4*)(B + (long)(bcol + lr) * K + k0 + lc);
            Bs[lc + 0][lr] = bv.x; Bs[lc + 1][lr] = bv.y;
            Bs[lc + 2][lr] = bv.z; Bs[lc + 3][lr] = bv.w;
        } else {
            int br = tid >> 5, bc = (tid & 31) * 4;
            *(float4*)&Bs[br][bc] = *(const float4*)(B + (long)(k0 + br) * N + bcol + bc);
        }
        __syncthreads();
#pragma unroll
        for (int kk = 0; kk < 8; kk++) {
            float ra[8], rb[8];
            *(float4*)&ra[0] = *(float4*)&As[kk][ty * 4];
            *(float4*)&ra[4] = *(float4*)&As[kk][64 + ty * 4];
            *(float4*)&rb[0] = *(float4*)&Bs[kk][tx * 4];
            *(float4*)&rb[4] = *(float4*)&Bs[kk][64 + tx * 4];
#pragma unroll
            for (int i = 0; i < 8; i++)
#pragma unroll
                for (int j = 0; j < 8; j++)
                    acc[i][j] += ra[i] * rb[j];
        }
        __syncthreads();
    }

#pragma unroll
    for (int i = 0; i < 8; i++) {
        int row = brow + ((i < 4) ? (ty * 4 + i) : (64 + ty * 4 + i - 4));
#pragma unroll
        for (int j = 0; j < 8; j++) {
            int col = bcol + ((j < 4) ? (tx * 4 + j) : (64 + tx * 4 + j - 4));
            float val = acc[i][j] * alpha;
            if (bias) val += bias[col];
            if (act == 1) val = gelu_exact(val);
            C[(long)row * ldc + col] = val;
        }
    }
}

// ---------------- causal softmax over rows of [H*B*T, T] ---------------------
__global__ void softmax_causal(float* __restrict__ w)
{
    long row = blockIdx.x;
    int  t   = (int)(row % Tq);
    float* p = w + row * (long)Tq;
    int tid = threadIdx.x;
    __shared__ float red[256];

    float vals[4];
    float vmax = -1e30f;
#pragma unroll
    for (int i = 0; i < 4; i++) {
        int j = tid + i * 256;
        float x = p[j];
        vals[i] = x;
        if (j <= t && x > vmax) vmax = x;
    }
    red[tid] = vmax; __syncthreads();
    for (int s = 128; s > 0; s >>= 1) {
        if (tid < s) red[tid] = fmaxf(red[tid], red[tid + s]);
        __syncthreads();
    }
    vmax = red[0]; __syncthreads();

    float sum = 0.f;
#pragma unroll
    for (int i = 0; i < 4; i++) {
        int j = tid + i * 256;
        float e = (j <= t) ? expf(vals[i] - vmax) : 0.f;
        vals[i] = e; sum += e;
    }
    red[tid] = sum; __syncthreads();
    for (int s = 128; s > 0; s >>= 1) {
        if (tid < s) red[tid] += red[tid + s];
        __syncthreads();
    }
    float inv = 1.f / red[0];
#pragma unroll
    for (int i = 0; i < 4; i++) p[tid + i * 256] = vals[i] * inv;
}

// ------------- residual + LayerNorm: t = x (+ y); out = t+ln(t) or ln(t) -----
__global__ void resln(const float* __restrict__ x, const float* __restrict__ y,
                      const float* __restrict__ g, const float* __restrict__ b,
                      float* __restrict__ out, int ln_only)
{
    long row = blockIdx.x;
    int tid = threadIdx.x;
    const float* px = x + row * (long)Dq;
    const float* py = y ? (y + row * (long)Dq) : nullptr;
    __shared__ float sh[Dq];
    __shared__ float red[256];

    float lsum = 0.f;
    for (int i = tid; i < Dq; i += 256) {
        float t = px[i] + (py ? py[i] : 0.f);
        sh[i] = t; lsum += t;
    }
    red[tid] = lsum; __syncthreads();
    for (int s = 128; s > 0; s >>= 1) { if (tid < s) red[tid] += red[tid + s]; __syncthreads(); }
    float mean = red[0] * (1.0f / Dq);
    __syncthreads();

    float lvar = 0.f;
    for (int i = tid; i < Dq; i += 256) { float d = sh[i] - mean; lvar += d * d; }
    red[tid] = lvar; __syncthreads();
    for (int s = 128; s > 0; s >>= 1) { if (tid < s) red[tid] += red[tid + s]; __syncthreads(); }
    float rstd = rsqrtf(red[0] * (1.0f / Dq) + 1e-5f);

    float* po = out + row * (long)Dq;
    for (int i = tid; i < Dq; i += 256) {
        float t = sh[i];
        float l = (t - mean) * rstd * g[i] + b[i];
        po[i] = ln_only ? l : (t + l);
    }
}

// -----------------------------------------------------------------------------
extern "C" void kernel_launch(void* const* d_in, const int* in_sizes, int n_in,
                              void* d_out, int out_size)
{
    const float* src = (const float*)d_in[0];
    const float* att = (const float*)d_in[1];
    const float* mWq = (const float*)d_in[2];
    const float* mbq = (const float*)d_in[3];
    const float* mWk = (const float*)d_in[4];
    const float* mbk = (const float*)d_in[5];
    const float* mWv = (const float*)d_in[6];
    const float* dWp = (const float*)d_in[7];
    const float* dbp = (const float*)d_in[8];
    const float* dWo = (const float*)d_in[9];
    const float* dbo = (const float*)d_in[10];
    const float* fW1 = (const float*)d_in[11];
    const float* fb1 = (const float*)d_in[12];
    const float* fW2 = (const float*)d_in[13];
    const float* fb2 = (const float*)d_in[14];
    const float* g1  = (const float*)d_in[15];
    const float* b1  = (const float*)d_in[16];
    const float* g2  = (const float*)d_in[17];
    const float* b2  = (const float*)d_in[18];
    float* out = (float*)d_out;

    float *q, *k, *v, *w, *ocat, *srcA, *wp, *o2, *o3, *trgf, *ln2, *h1, *ff;
    cudaGetSymbolAddress((void**)&q,    g_q);
    cudaGetSymbolAddress((void**)&k,    g_k);
    cudaGetSymbolAddress((void**)&v,    g_v);
    cudaGetSymbolAddress((void**)&w,    g_w);
    cudaGetSymbolAddress((void**)&ocat, g_ocat);
    cudaGetSymbolAddress((void**)&srcA, g_srcA);
    cudaGetSymbolAddress((void**)&wp,   g_wp);
    cudaGetSymbolAddress((void**)&o2,   g_o2);
    cudaGetSymbolAddress((void**)&o3,   g_o3);
    cudaGetSymbolAddress((void**)&trgf, g_trgf);
    cudaGetSymbolAddress((void**)&ln2,  g_ln2);
    cudaGetSymbolAddress((void**)&h1,   g_h1);
    cudaGetSymbolAddress((void**)&ff,   g_ff);

    dim3 blk(256);
    const long BTHS = (long)BT * HSq;     // 8388608
    const long THS  = (long)Tq * HSq;     // 1048576
    const long BTT  = (long)Bq * Tq * Tq; // 8388608
    const long TT   = (long)Tq * Tq;      // 1048576
    const long BTD  = (long)BT * Dq;      // 33554432
    const long TD   = (long)Tq * Dq;      // 4194304
    const long WHS  = (long)Dq * HSq;     // per-head weight stride (mW*)
    const long WPD  = (long)HSq * Dq;     // per-head dWp stride

    // 1-3) Q,K,V projections per head: [8192,4096]@[4096,1024]
    {
        dim3 grd(HSq / 128, BT / 128, Hq);
        sgemm<false><<<grd, blk>>>(src, mWq, mbq, q, BT, HSq, Dq, HSq, 1,
                                   0, 0, WHS, 0, BTHS, 0, HSq, 1.0f, 0);
        sgemm<false><<<grd, blk>>>(src, mWk, mbk, k, BT, HSq, Dq, HSq, 1,
                                   0, 0, WHS, 0, BTHS, 0, HSq, 1.0f, 0);
        sgemm<false><<<grd, blk>>>(src, mWv, nullptr, v, BT, HSq, Dq, HSq, 1,
                                   0, 0, WHS, 0, BTHS, 0, 0, 1.0f, 0);
    }
    // 4) scores: per (h,b): [1024,1024] = q@k^T * sqrt(HS)
    {
        dim3 grd(Tq / 128, Tq / 128, Hq * Bq);
        sgemm<true><<<grd, blk>>>(q, k, nullptr, w, Tq, Tq, HSq, Tq, Bq,
                                  BTHS, THS, BTHS, THS, BTT, TT, 0, 32.0f, 0);
    }
    // 5) causal softmax
    softmax_causal<<<Hq * Bq * Tq, blk>>>(w);
    // 6) o = a@v, written to concatenated layout [B][T][h*HS+e]
    {
        dim3 grd(HSq / 128, Tq / 128, Hq * Bq);
        sgemm<false><<<grd, blk>>>(w, v, nullptr, ocat, Tq, HSq, Tq, Dq, Bq,
                                   BTT, TT, BTHS, THS, (long)HSq, TD, 0, 1.0f, 0);
    }
    // 7) srcA = (src+o) + ln(src+o)
    resln<<<BT, blk>>>(src, ocat, g1, b1, srcA, 0);
    // 8) wp[h] = att@dWp[h] + dbp[h]: [8192,1024]@[1024,4096]
    {
        dim3 grd(Dq / 128, BT / 128, Hq);
        sgemm<false><<<grd, blk>>>(att, dWp, dbp, wp, BT, Dq, HSq, Dq, 1,
                                   0, 0, WPD, 0, BTD, 0, Dq, 1.0f, 0);
    }
    // 9) o2 = wp@srcA^T per (h,b), written to [B][T][h*T+u]
    {
        dim3 grd(Tq / 128, Tq / 128, Hq * Bq);
        sgemm<true><<<grd, blk>>>(wp, srcA, nullptr, o2, Tq, Tq, Dq, Dq, Bq,
                                  BTD, TD, 0, TD, (long)Tq, TD, 0, 1.0f, 0);
    }
    // 10) o3 = o2@dWo + dbo
    {
        dim3 grd(Dq / 128, BT / 128, 1);
        sgemm<false><<<grd, blk>>>(o2, dWo, dbo, o3, BT, Dq, Dq, Dq, 1,
                                   0, 0, 0, 0, 0, 0, 0, 1.0f, 0);
    }
    // 11) trg_f = (srcA+o3) + ln(srcA+o3)
    resln<<<BT, blk>>>(srcA, o3, g1, b1, trgf, 0);
    // 12) ln2 = ln(trg_f, g2, b2)
    resln<<<BT, blk>>>(trgf, nullptr, g2, b2, ln2, 1);
    // 13) h1 = gelu(ln2@fW1 + fb1): [8192,4096]@[4096,20480]
    {
        dim3 grd(FFq / 128, BT / 128, 1);
        sgemm<false><<<grd, blk>>>(ln2, fW1, fb1, h1, BT, FFq, Dq, FFq, 1,
                                   0, 0, 0, 0, 0, 0, 0, 1.0f, 1);
    }
    // 14) ff = h1@fW2 + fb2: [8192,20480]@[20480,4096]
    {
        dim3 grd(Dq / 128, BT / 128, 1);
        sgemm<false><<<grd, blk>>>(h1, fW2, fb2, ff, BT, Dq, FFq, Dq, 1,
                                   0, 0, 0, 0, 0, 0, 0, 1.0f, 0);
    }
    // 15) out = ln(trg_f + ff, g2, b2)
    resln<<<BT, blk>>>(trgf, ff, g2, b2, out, 1);
}